// round 13
// baseline (speedup 1.0000x reference)
#include <cuda_runtime.h>

// x: (N=8, M=32, C=128, H=32, W=32) fp32.  D = H*W = 1024.
// 4096 independent classical Gram-Schmidt problems, each over 8 vectors of
// length 1024.
//
// Two problems per block (grid=2048, 256 threads), register double-buffer:
// B's 8 LDG.128 are issued right after A's Gram-STS and ride the scoreboard
// through A's reduce/recursion/apply phases, so each CTA keeps DRAM busy
// during its compute window.  Compute pipeline per problem is the proven R3
// one (full-width Gram partials, cooperative reduce, warp-0 triangular
// recursion, direct apply).
#define NV 8
#define DLEN 1024
#define NPROB 4096
#define NSTRIDE_F4 (NPROB * DLEN / 4)   // 1048576 float4 between n-slices
#define NG 36
#define GRID 2048

__device__ __forceinline__ float dot4(float4 a, float4 b) {
    return a.x * b.x + a.y * b.y + a.z * b.z + a.w * b.w;
}

struct Smem {
    float part[NG][256];  // 36KB Gram partials
    float Gf[NG];
    float Tm[NG];
};

__device__ __forceinline__ void gram_sts(const float4 v[NV], Smem* s, int tid) {
    #pragma unroll
    for (int i = 0; i < NV; i++) {
        #pragma unroll
        for (int j = 0; j <= i; j++) {
            s->part[i * (i + 1) / 2 + j][tid] = dot4(v[i], v[j]);
        }
    }
}

__device__ __forceinline__ void reduce36(Smem* s, int lane, int warp) {
    for (int t = warp; t < NG; t += 8) {
        const float4* row = reinterpret_cast<const float4*>(s->part[t]);
        float4 a = row[lane];
        float4 b = row[lane + 32];
        float r = (a.x + a.y) + (a.z + a.w) + (b.x + b.y) + (b.z + b.w);
        r += __shfl_xor_sync(0xffffffffu, r, 16);
        r += __shfl_xor_sync(0xffffffffu, r, 8);
        r += __shfl_xor_sync(0xffffffffu, r, 4);
        r += __shfl_xor_sync(0xffffffffu, r, 2);
        r += __shfl_xor_sync(0xffffffffu, r, 1);
        if (lane == 0) s->Gf[t] = r;
    }
}

__device__ __forceinline__ void recursion(Smem* s, int lane) {
    float G[NG];
    #pragma unroll
    for (int t = 0; t < NG; t++) G[t] = s->Gf[t];

    float T[NG];
    {
        float inv = (G[0] > 0.0f) ? rsqrtf(G[0]) : 0.0f;
        T[0] = inv;
    }
    #pragma unroll
    for (int i = 1; i < NV; i++) {
        float c[NV];
        #pragma unroll
        for (int j = 0; j < i; j++) {
            float acc = 0.0f;
            #pragma unroll
            for (int k = 0; k <= j; k++)
                acc += T[j * (j + 1) / 2 + k] * G[i * (i + 1) / 2 + k];
            c[j] = acc;
        }
        float n2 = G[i * (i + 1) / 2 + i];
        #pragma unroll
        for (int j = 0; j < i; j++) n2 -= c[j] * c[j];
        float inv = (n2 > 0.0f) ? rsqrtf(n2) : 0.0f;

        #pragma unroll
        for (int k = 0; k < i; k++) {
            float acc = 0.0f;
            #pragma unroll
            for (int j = k; j < i; j++)
                acc -= c[j] * T[j * (j + 1) / 2 + k];
            T[i * (i + 1) / 2 + k] = acc * inv;
        }
        T[i * (i + 1) / 2 + i] = inv;
    }
    if (lane == 0) {
        #pragma unroll
        for (int t = 0; t < NG; t++) s->Tm[t] = T[t];
    }
}

__device__ __forceinline__ void apply_store(const float4 v[NV],
                                            float4* __restrict__ dst,
                                            Smem* s) {
    #pragma unroll
    for (int i = 0; i < NV; i++) {
        float4 acc = make_float4(0.0f, 0.0f, 0.0f, 0.0f);
        #pragma unroll
        for (int k = 0; k <= i; k++) {
            float t = s->Tm[i * (i + 1) / 2 + k];
            acc.x += t * v[k].x;
            acc.y += t * v[k].y;
            acc.z += t * v[k].z;
            acc.w += t * v[k].w;
        }
        __stcs(&dst[(size_t)i * NSTRIDE_F4], acc);
    }
}

__global__ void __launch_bounds__(256, 3)
gram_schmidt_kernel(const float* __restrict__ x, float* __restrict__ out) {
    const int tid  = threadIdx.x;
    const int lane = tid & 31;
    const int warp = tid >> 5;

    __shared__ Smem s;

    const int pA = blockIdx.x;
    const int pB = blockIdx.x + GRID;

    const float4* __restrict__ xin4 = reinterpret_cast<const float4*>(x);
    float4* __restrict__ out4 = reinterpret_cast<float4*>(out);

    // ---- problem A: load + Gram partials ----
    float4 vA[NV];
    {
        const float4* src = xin4 + (size_t)pA * (DLEN / 4) + tid;
        #pragma unroll
        for (int n = 0; n < NV; n++) vA[n] = src[(size_t)n * NSTRIDE_F4];
    }
    gram_sts(vA, &s, tid);

    // ---- issue problem B's loads NOW; they fly through A's compute ----
    float4 vB[NV];
    {
        const float4* src = xin4 + (size_t)pB * (DLEN / 4) + tid;
        #pragma unroll
        for (int n = 0; n < NV; n++) vB[n] = src[(size_t)n * NSTRIDE_F4];
    }

    // ---- finish problem A ----
    __syncthreads();
    reduce36(&s, lane, warp);
    __syncthreads();
    if (warp == 0) recursion(&s, lane);
    __syncthreads();
    apply_store(vA, out4 + (size_t)pA * (DLEN / 4) + tid, &s);

    // ---- problem B (data already resident in registers) ----
    gram_sts(vB, &s, tid);
    __syncthreads();
    reduce36(&s, lane, warp);
    __syncthreads();
    if (warp == 0) recursion(&s, lane);
    __syncthreads();
    apply_store(vB, out4 + (size_t)pB * (DLEN / 4) + tid, &s);
}

extern "C" void kernel_launch(void* const* d_in, const int* in_sizes, int n_in,
                              void* d_out, int out_size) {
    const float* x = (const float*)d_in[0];
    float* out = (float*)d_out;
    gram_schmidt_kernel<<<GRID, 256>>>(x, out);
}

// round 14
// speedup vs baseline: 1.1792x; 1.1792x over previous
#include <cuda_runtime.h>

// x: (N=8, M=32, C=128, H=32, W=32) fp32.  D = H*W = 1024.
// 4096 independent classical Gram-Schmidt problems (one per (m,c)),
// each over NV=8 vectors of length 1024.
//
// R3 structure (empirically optimal family member): one block (256 threads)
// per problem, 1 float4/thread/vector, 4 CTAs/SM.
// This revision shortens the serial reduce phase: each warp's 4-5 entry
// reductions are fully unrolled into independent, interleaved SHFL chains
// (SHFL lat=26cyc; sequential chains cost ~650cyc, interleaved ~170cyc),
// shrinking the per-CTA DRAM-idle compute window.
#define NV 8
#define DLEN 1024
#define NPROB 4096
#define NSTRIDE_F4 (NPROB * DLEN / 4)   // 1048576 float4 between n-slices
#define NG 36                           // lower-triangular entries

__device__ __forceinline__ float dot4(float4 a, float4 b) {
    return a.x * b.x + a.y * b.y + a.z * b.z + a.w * b.w;
}

__global__ void __launch_bounds__(256, 4)
gram_schmidt_kernel(const float* __restrict__ x, float* __restrict__ out) {
    const int p    = blockIdx.x;
    const int tid  = threadIdx.x;
    const int lane = tid & 31;
    const int warp = tid >> 5;

    const float4* __restrict__ xin =
        reinterpret_cast<const float4*>(x) + (size_t)p * (DLEN / 4) + tid;
    float4* __restrict__ xout =
        reinterpret_cast<float4*>(out) + (size_t)p * (DLEN / 4) + tid;

    __shared__ float part[NG][256];  // 36KB: per-thread Gram partials
    __shared__ float Gf[NG];         // reduced Gram (packed lower tri)
    __shared__ float Tm[NG];         // GS transform matrix (packed lower tri)

    // ---- A: load all 8 vectors (batched LDG.128) + Gram partials ----
    float4 v[NV];
    #pragma unroll
    for (int n = 0; n < NV; n++) v[n] = xin[(size_t)n * NSTRIDE_F4];

    #pragma unroll
    for (int i = 0; i < NV; i++) {
        #pragma unroll
        for (int j = 0; j <= i; j++) {
            part[i * (i + 1) / 2 + j][tid] = dot4(v[i], v[j]);
        }
    }
    __syncthreads();

    // ---- B: cooperative reduction, warp w owns entries w, w+8, ..., ----
    // fully unrolled so the 4-5 SHFL chains run interleaved (ILP), not
    // back-to-back.
    {
        float s[5];
        // gather + intra-thread sum for all owned entries first (LDS batched)
        #pragma unroll
        for (int u = 0; u < 5; u++) {
            const int t = warp + u * 8;
            if (t < NG) {
                const float4* row = reinterpret_cast<const float4*>(part[t]);
                float4 a = row[lane];
                float4 b = row[lane + 32];
                s[u] = (a.x + a.y) + (a.z + a.w) + (b.x + b.y) + (b.z + b.w);
            } else {
                s[u] = 0.0f;
            }
        }
        // interleaved butterfly chains
        #pragma unroll
        for (int m = 16; m >= 1; m >>= 1) {
            #pragma unroll
            for (int u = 0; u < 5; u++) {
                s[u] += __shfl_xor_sync(0xffffffffu, s[u], m);
            }
        }
        if (lane == 0) {
            #pragma unroll
            for (int u = 0; u < 5; u++) {
                const int t = warp + u * 8;
                if (t < NG) Gf[t] = s[u];
            }
        }
    }
    __syncthreads();

    // ---- C: warp 0 computes the triangular recursion (replicated lanes) ----
    if (warp == 0) {
        float G[NG];
        #pragma unroll
        for (int t = 0; t < NG; t++) G[t] = Gf[t];  // broadcast LDS

        float T[NG];
        {
            float inv = (G[0] > 0.0f) ? rsqrtf(G[0]) : 0.0f;
            T[0] = inv;
        }
        #pragma unroll
        for (int i = 1; i < NV; i++) {
            float c[NV];
            #pragma unroll
            for (int j = 0; j < i; j++) {
                float s = 0.0f;
                #pragma unroll
                for (int k = 0; k <= j; k++)
                    s += T[j * (j + 1) / 2 + k] * G[i * (i + 1) / 2 + k];
                c[j] = s;
            }
            float n2 = G[i * (i + 1) / 2 + i];
            #pragma unroll
            for (int j = 0; j < i; j++) n2 -= c[j] * c[j];
            float inv = (n2 > 0.0f) ? rsqrtf(n2) : 0.0f;

            #pragma unroll
            for (int k = 0; k < i; k++) {
                float s = 0.0f;
                #pragma unroll
                for (int j = k; j < i; j++)
                    s -= c[j] * T[j * (j + 1) / 2 + k];
                T[i * (i + 1) / 2 + k] = s * inv;
            }
            T[i * (i + 1) / 2 + i] = inv;
        }
        if (lane == 0) {
            #pragma unroll
            for (int t = 0; t < NG; t++) Tm[t] = T[t];
        }
    }
    __syncthreads();

    // ---- D: apply b_i = sum_{k<=i} T[i][k] v_k, streaming store ----
    #pragma unroll
    for (int i = 0; i < NV; i++) {
        float4 acc = make_float4(0.0f, 0.0f, 0.0f, 0.0f);
        #pragma unroll
        for (int k = 0; k <= i; k++) {
            float t = Tm[i * (i + 1) / 2 + k];  // LDS broadcast
            acc.x += t * v[k].x;
            acc.y += t * v[k].y;
            acc.z += t * v[k].z;
            acc.w += t * v[k].w;
        }
        __stcs(&xout[(size_t)i * NSTRIDE_F4], acc);
    }
}

extern "C" void kernel_launch(void* const* d_in, const int* in_sizes, int n_in,
                              void* d_out, int out_size) {
    const float* x = (const float*)d_in[0];
    float* out = (float*)d_out;
    gram_schmidt_kernel<<<NPROB, 256>>>(x, out);
}